// round 2
// baseline (speedup 1.0000x reference)
#include <cuda_runtime.h>
#include <cuda_bf16.h>
#include <math.h>

#define B   2
#define T   2048
#define C   2048
#define H   16
#define KV  4
#define D   128
#define LP  64
#define GROUPS (H / KV)
#define LSEQ (T - LP)            // 1984
#define SCALE 0.08838834764831845f   // 1/sqrt(128)

// ---------------- scratch (static device globals: allowed) ----------------
__device__ float g_q[(size_t)B * H * T * D];          // 33.5 MB  [B,H,T,D]
__device__ float g_k[(size_t)B * KV * T * D];         //  8.4 MB  [B,KV,T,D]
__device__ float g_v[(size_t)B * KV * T * D];         //  8.4 MB  [B,KV,T,D]
__device__ float g_s[(size_t)B * H * T * T];          // 537 MB   [B,H,T,T]
__device__ float g_o[(size_t)B * T * H * D];          // 33.5 MB  [B,T,H*D]

// ===========================================================================
// Generic 64x64 tiled GEMM:  out = A(MxK) @ W(KxN) + bias
// 256 threads (16x16), each computes 4x4. K tile = 16. All dims divide tiles.
// NH > 0: scatter output column n -> (head h = n/D, d = n%D), row m -> (b,t):
//         out[((b*NH + h)*T + t)*D + d]   (used for Q/K/V projections)
// NH == 0: plain row-major out[m*N + n]   (used for final projection)
// ===========================================================================
__global__ void __launch_bounds__(256)
gemm_proj(const float* __restrict__ A, const float* __restrict__ W,
          const float* __restrict__ bias, float* __restrict__ out,
          int M, int N, int K, int NH)
{
    __shared__ float As[16][64];
    __shared__ float Bs[16][64];

    const int tx = threadIdx.x, ty = threadIdx.y;
    const int tid = ty * 16 + tx;
    const int m0 = blockIdx.y * 64, n0 = blockIdx.x * 64;

    const int ar = tid >> 2;            // 0..63 row of A tile
    const int ak = (tid & 3) * 4;       // k offset (float4)
    const int bk = tid >> 4;            // 0..15 k row of W tile
    const int bn = (tid & 15) * 4;      // col offset (float4)

    float acc[4][4] = {};

    for (int k0 = 0; k0 < K; k0 += 16) {
        float4 av = *reinterpret_cast<const float4*>(&A[(size_t)(m0 + ar) * K + k0 + ak]);
        As[ak + 0][ar] = av.x; As[ak + 1][ar] = av.y;
        As[ak + 2][ar] = av.z; As[ak + 3][ar] = av.w;
        *reinterpret_cast<float4*>(&Bs[bk][bn]) =
            *reinterpret_cast<const float4*>(&W[(size_t)(k0 + bk) * N + n0 + bn]);
        __syncthreads();
#pragma unroll
        for (int kk = 0; kk < 16; kk++) {
            float4 ra = *reinterpret_cast<const float4*>(&As[kk][ty * 4]);
            float4 rb = *reinterpret_cast<const float4*>(&Bs[kk][tx * 4]);
            float a[4] = {ra.x, ra.y, ra.z, ra.w};
            float b[4] = {rb.x, rb.y, rb.z, rb.w};
#pragma unroll
            for (int i = 0; i < 4; i++)
#pragma unroll
                for (int j = 0; j < 4; j++)
                    acc[i][j] += a[i] * b[j];
        }
        __syncthreads();
    }

#pragma unroll
    for (int i = 0; i < 4; i++) {
        int m = m0 + ty * 4 + i;
#pragma unroll
        for (int j = 0; j < 4; j++) {
            int n = n0 + tx * 4 + j;
            float val = acc[i][j] + (bias ? bias[n] : 0.f);
            if (NH > 0) {
                int b = m / T, t = m % T;
                int h = n / D, d = n % D;
                out[(((size_t)(b * NH + h)) * T + t) * D + d] = val;
            } else {
                out[(size_t)m * N + n] = val;
            }
        }
    }
}

// ===========================================================================
// RoPE on [B,NH,T,D] buffer, positions t >= LP.
// out[:64] = x1*c1 - x2*s1 ; out[64:] = x2*c2 + x1*s2
// grid covers B*NH*(T-LP)*64 threads.
// ===========================================================================
__global__ void __launch_bounds__(256)
rope_kernel(float* __restrict__ x, const float* __restrict__ cosp,
            const float* __restrict__ sinp, int NH)
{
    int idx = blockIdx.x * 256 + threadIdx.x;
    int d = idx & 63;
    int rest = idx >> 6;
    int t = rest % LSEQ + LP;
    int bh = rest / LSEQ;
    int b = bh / NH, h = bh % NH;

    size_t base  = ((size_t)(b * NH + h) * T + t) * D;
    size_t cbase = ((size_t)b * LSEQ + (t - LP)) * D;

    float x1 = x[base + d], x2 = x[base + d + 64];
    float c1 = cosp[cbase + d],      s1 = sinp[cbase + d];
    float c2 = cosp[cbase + d + 64], s2 = sinp[cbase + d + 64];
    x[base + d]      = x1 * c1 - x2 * s1;
    x[base + d + 64] = x2 * c2 + x1 * s2;
}

// ===========================================================================
// Scores: S[bh,i,j] = SCALE * dot(Q[bh,i,:], K[b,h/G, j, :]) + bias_mask(i,j)
// bias_mask = 1.0 if (j < LP) || (i >= LP && j <= i) else 0.0  (ADDITIVE)
// 64x64 tile over (i,j), K-dim = D = 128.
// ===========================================================================
__global__ void __launch_bounds__(256)
gemm_scores(const float* __restrict__ q, const float* __restrict__ k,
            float* __restrict__ s)
{
    int bh = blockIdx.z;
    int b = bh / H, h = bh % H;
    const float* Q  = q + (size_t)(b * H + h) * T * D;
    const float* Kp = k + (size_t)(b * KV + h / GROUPS) * T * D;
    float* S = s + (size_t)bh * T * T;

    __shared__ float As[16][64];
    __shared__ float Bs[16][64];

    const int tx = threadIdx.x, ty = threadIdx.y;
    const int tid = ty * 16 + tx;
    const int i0 = blockIdx.y * 64, j0 = blockIdx.x * 64;
    const int r = tid >> 2;
    const int kq = (tid & 3) * 4;

    float acc[4][4] = {};

    for (int k0 = 0; k0 < D; k0 += 16) {
        float4 qv = *reinterpret_cast<const float4*>(&Q[(size_t)(i0 + r) * D + k0 + kq]);
        As[kq + 0][r] = qv.x; As[kq + 1][r] = qv.y;
        As[kq + 2][r] = qv.z; As[kq + 3][r] = qv.w;
        float4 kv = *reinterpret_cast<const float4*>(&Kp[(size_t)(j0 + r) * D + k0 + kq]);
        Bs[kq + 0][r] = kv.x; Bs[kq + 1][r] = kv.y;
        Bs[kq + 2][r] = kv.z; Bs[kq + 3][r] = kv.w;
        __syncthreads();
#pragma unroll
        for (int kk = 0; kk < 16; kk++) {
            float4 ra = *reinterpret_cast<const float4*>(&As[kk][ty * 4]);
            float4 rb = *reinterpret_cast<const float4*>(&Bs[kk][tx * 4]);
            float a[4] = {ra.x, ra.y, ra.z, ra.w};
            float bb[4] = {rb.x, rb.y, rb.z, rb.w};
#pragma unroll
            for (int i = 0; i < 4; i++)
#pragma unroll
                for (int j = 0; j < 4; j++)
                    acc[i][j] += a[i] * bb[j];
        }
        __syncthreads();
    }

#pragma unroll
    for (int ii = 0; ii < 4; ii++) {
        int i = i0 + ty * 4 + ii;
#pragma unroll
        for (int jj = 0; jj < 4; jj++) {
            int j = j0 + tx * 4 + jj;
            float bias = ((j < LP) || (i >= LP && j <= i)) ? 1.0f : 0.0f;
            S[(size_t)i * T + j] = acc[ii][jj] * SCALE + bias;
        }
    }
}

// ===========================================================================
// Row softmax over T=2048 elements. One block (256 thr) per row, 8 per thread.
// ===========================================================================
__global__ void __launch_bounds__(256)
softmax_rows(float* __restrict__ s)
{
    float* row = s + (size_t)blockIdx.x * T;
    __shared__ float red[256];
    int tid = threadIdx.x;

    float v[8];
    float mx = -1e30f;
#pragma unroll
    for (int i = 0; i < 8; i++) { v[i] = row[tid + i * 256]; mx = fmaxf(mx, v[i]); }
    red[tid] = mx; __syncthreads();
    for (int st = 128; st > 0; st >>= 1) {
        if (tid < st) red[tid] = fmaxf(red[tid], red[tid + st]);
        __syncthreads();
    }
    mx = red[0]; __syncthreads();

    float sum = 0.f;
#pragma unroll
    for (int i = 0; i < 8; i++) { v[i] = __expf(v[i] - mx); sum += v[i]; }
    red[tid] = sum; __syncthreads();
    for (int st = 128; st > 0; st >>= 1) {
        if (tid < st) red[tid] += red[tid + st];
        __syncthreads();
    }
    float inv = 1.0f / red[0];
#pragma unroll
    for (int i = 0; i < 8; i++) row[tid + i * 256] = v[i] * inv;
}

// ===========================================================================
// PV: O[b,t,h*D+d] = sum_j P[bh,t,j] * V[b,h/G,j,d].  M=T, N=D=128, K=T.
// ===========================================================================
__global__ void __launch_bounds__(256)
gemm_pv(const float* __restrict__ s, const float* __restrict__ v,
        float* __restrict__ o)
{
    int bh = blockIdx.z;
    int b = bh / H, h = bh % H;
    const float* P = s + (size_t)bh * T * T;
    const float* V = v + (size_t)(b * KV + h / GROUPS) * T * D;

    __shared__ float As[16][64];
    __shared__ float Bs[16][64];

    const int tx = threadIdx.x, ty = threadIdx.y;
    const int tid = ty * 16 + tx;
    const int i0 = blockIdx.y * 64, n0 = blockIdx.x * 64;

    const int ar = tid >> 2;
    const int ak = (tid & 3) * 4;
    const int bk = tid >> 4;
    const int bn = (tid & 15) * 4;

    float acc[4][4] = {};

    for (int k0 = 0; k0 < T; k0 += 16) {
        float4 av = *reinterpret_cast<const float4*>(&P[(size_t)(i0 + ar) * T + k0 + ak]);
        As[ak + 0][ar] = av.x; As[ak + 1][ar] = av.y;
        As[ak + 2][ar] = av.z; As[ak + 3][ar] = av.w;
        *reinterpret_cast<float4*>(&Bs[bk][bn]) =
            *reinterpret_cast<const float4*>(&V[(size_t)(k0 + bk) * D + n0 + bn]);
        __syncthreads();
#pragma unroll
        for (int kk = 0; kk < 16; kk++) {
            float4 ra = *reinterpret_cast<const float4*>(&As[kk][ty * 4]);
            float4 rb = *reinterpret_cast<const float4*>(&Bs[kk][tx * 4]);
            float a[4] = {ra.x, ra.y, ra.z, ra.w};
            float bb[4] = {rb.x, rb.y, rb.z, rb.w};
#pragma unroll
            for (int i = 0; i < 4; i++)
#pragma unroll
                for (int j = 0; j < 4; j++)
                    acc[i][j] += a[i] * bb[j];
        }
        __syncthreads();
    }

#pragma unroll
    for (int ii = 0; ii < 4; ii++) {
        int i = i0 + ty * 4 + ii;
#pragma unroll
        for (int jj = 0; jj < 4; jj++) {
            int n = n0 + tx * 4 + jj;      // 0..127 = d
            o[((size_t)b * T + i) * (H * D) + h * D + n] = acc[ii][jj];
        }
    }
}

// ===========================================================================
// Launch
// ===========================================================================
extern "C" void kernel_launch(void* const* d_in, const int* in_sizes, int n_in,
                              void* d_out, int out_size)
{
    (void)in_sizes; (void)n_in; (void)out_size;
    const float* hs   = (const float*)d_in[0];
    const float* cosp = (const float*)d_in[1];
    const float* sinp = (const float*)d_in[2];
    const float* Wq   = (const float*)d_in[3];
    const float* bq   = (const float*)d_in[4];
    const float* Wk   = (const float*)d_in[5];
    const float* bk   = (const float*)d_in[6];
    const float* Wv   = (const float*)d_in[7];
    const float* bv   = (const float*)d_in[8];
    const float* Wo   = (const float*)d_in[9];
    float* out = (float*)d_out;

    float *q, *k, *v, *s, *o;
    cudaGetSymbolAddress((void**)&q, g_q);
    cudaGetSymbolAddress((void**)&k, g_k);
    cudaGetSymbolAddress((void**)&v, g_v);
    cudaGetSymbolAddress((void**)&s, g_s);
    cudaGetSymbolAddress((void**)&o, g_o);

    dim3 thr(16, 16);
    const int M = B * T;  // 4096

    // QKV projections (scatter to [B,heads,T,D])
    gemm_proj<<<dim3((H * D) / 64, M / 64), thr>>>(hs, Wq, bq, q, M, H * D, C, H);
    gemm_proj<<<dim3((KV * D) / 64, M / 64), thr>>>(hs, Wk, bk, k, M, KV * D, C, KV);
    gemm_proj<<<dim3((KV * D) / 64, M / 64), thr>>>(hs, Wv, bv, v, M, KV * D, C, KV);

    // RoPE on q (H heads) and k (KV heads), positions >= LP
    rope_kernel<<<(B * H * LSEQ * 64) / 256, 256>>>(q, cosp, sinp, H);
    rope_kernel<<<(B * KV * LSEQ * 64) / 256, 256>>>(k, cosp, sinp, KV);

    // S = scale * Q K^T + additive prefix-causal bias
    gemm_scores<<<dim3(T / 64, T / 64, B * H), thr>>>(q, k, s);

    // row softmax
    softmax_rows<<<B * H * T, 256>>>(s);

    // O = P V  -> [B,T,H*D]
    gemm_pv<<<dim3(D / 64, T / 64, B * H), thr>>>(s, v, o);

    // final projection (no bias)
    gemm_proj<<<dim3(C / 64, M / 64), thr>>>(o, Wo, nullptr, out, M, C, H * D, 0);
}

// round 4
// speedup vs baseline: 1.2803x; 1.2803x over previous
#include <cuda_runtime.h>
#include <cuda_bf16.h>
#include <math.h>
#include <stdint.h>

#define B   2
#define T   2048
#define C   2048
#define H   16
#define KV  4
#define D   128
#define LP  64
#define GROUPS (H / KV)
#define LSEQ (T - LP)            // 1984
#define SCALE 0.08838834764831845f   // 1/sqrt(128)

// ---------------- scratch (static device globals: allowed) ----------------
__device__ float g_q[(size_t)B * H * T * D];          // [B,H,T,D]
__device__ float g_k[(size_t)B * KV * T * D];         // [B,KV,T,D]
__device__ float g_v[(size_t)B * KV * T * D];         // [B,KV,T,D]
__device__ float g_s[(size_t)B * H * T * T];          // [B,H,T,T] 537 MB
__device__ float g_o[(size_t)B * T * H * D];          // [B,T,H*D]

// ---------------------------------------------------------------------------
// tf32 helpers
// ---------------------------------------------------------------------------
__device__ __forceinline__ uint32_t f2tf(float x) {
    uint32_t r;
    asm("cvt.rna.tf32.f32 %0, %1;" : "=r"(r) : "f"(x));
    return r;
}

__device__ __forceinline__ void mma_tf32(float c[4],
                                         const uint32_t a[4],
                                         const uint32_t b[2]) {
    asm volatile(
        "mma.sync.aligned.m16n8k8.row.col.f32.tf32.tf32.f32 "
        "{%0,%1,%2,%3},{%4,%5,%6,%7},{%8,%9},{%0,%1,%2,%3};"
        : "+f"(c[0]), "+f"(c[1]), "+f"(c[2]), "+f"(c[3])
        : "r"(a[0]), "r"(a[1]), "r"(a[2]), "r"(a[3]), "r"(b[0]), "r"(b[1]));
}

// ---------------------------------------------------------------------------
// Core: 128x128 output tile, K-loop step 16, 256 threads (8 warps, 2x4 layout,
// 64x32 warp tile). 3xTF32 split for fp32-level accuracy.
// A: row-major [*, lda], tile rows m0.. ; B:
//   TRANSB=false: row-major [k][n] with stride ldb (tile cols n0..)
//   TRANSB=true : row-major [n][k] with stride ldb (i.e. B^T; tile rows n0..)
// ---------------------------------------------------------------------------
template<bool TRANSB>
__device__ __forceinline__ void gemm_core(const float* __restrict__ A,
                                          const float* __restrict__ Bm,
                                          int Kdim, int lda, int ldb,
                                          int m0, int n0,
                                          float acc[4][4][4])
{
    __shared__ float As[16][136];
    __shared__ float Bs[16][136];

    const int tid  = threadIdx.x;
    const int lane = tid & 31;
    const int warp = tid >> 5;
    const int gid  = lane >> 2;        // 0..7
    const int tig  = lane & 3;         // 0..3
    const int wm   = (warp >> 2) * 64; // warp M offset (0/64)
    const int wn   = (warp & 3) * 32;  // warp N offset (0/32/64/96)

    const int ar  = tid >> 2;          // 0..63 (A/B^T tile row)
    const int ac4 = (tid & 3) * 4;     // k offset, float4
    const int br  = tid >> 4;          // 0..15 (row-major B k row)
    const int bc  = (tid & 15) * 4;    // n offset, float4

    for (int k0 = 0; k0 < Kdim; k0 += 16) {
        // ---- load A tile (transposed into [k][m]) ----
#pragma unroll
        for (int half = 0; half < 2; half++) {
            int row = ar + half * 64;
            float4 v = *reinterpret_cast<const float4*>(
                &A[(size_t)(m0 + row) * lda + k0 + ac4]);
            As[ac4 + 0][row] = v.x; As[ac4 + 1][row] = v.y;
            As[ac4 + 2][row] = v.z; As[ac4 + 3][row] = v.w;
        }
        // ---- load B tile into [k][n] ----
        if (TRANSB) {
#pragma unroll
            for (int half = 0; half < 2; half++) {
                int row = ar + half * 64;
                float4 v = *reinterpret_cast<const float4*>(
                    &Bm[(size_t)(n0 + row) * ldb + k0 + ac4]);
                Bs[ac4 + 0][row] = v.x; Bs[ac4 + 1][row] = v.y;
                Bs[ac4 + 2][row] = v.z; Bs[ac4 + 3][row] = v.w;
            }
        } else {
#pragma unroll
            for (int half = 0; half < 2; half++) {
                *reinterpret_cast<float4*>(&Bs[br][bc + half * 64]) =
                    *reinterpret_cast<const float4*>(
                        &Bm[(size_t)(k0 + br) * ldb + n0 + bc + half * 64]);
            }
        }
        __syncthreads();

#pragma unroll
        for (int ks = 0; ks < 2; ks++) {
            uint32_t ahi[4][4], alo[4][4];
#pragma unroll
            for (int mf = 0; mf < 4; mf++)
#pragma unroll
                for (int r = 0; r < 4; r++) {
                    int krow = ks * 8 + tig + (r >> 1) * 4;
                    int mcol = wm + mf * 16 + gid + (r & 1) * 8;
                    float a = As[krow][mcol];
                    uint32_t hi = f2tf(a);
                    ahi[mf][r] = hi;
                    alo[mf][r] = f2tf(a - __uint_as_float(hi));
                }
            uint32_t bhi[4][2], blo[4][2];
#pragma unroll
            for (int nf = 0; nf < 4; nf++)
#pragma unroll
                for (int r = 0; r < 2; r++) {
                    int krow = ks * 8 + tig + r * 4;
                    int ncol = wn + nf * 8 + gid;
                    float b = Bs[krow][ncol];
                    uint32_t hi = f2tf(b);
                    bhi[nf][r] = hi;
                    blo[nf][r] = f2tf(b - __uint_as_float(hi));
                }
#pragma unroll
            for (int mf = 0; mf < 4; mf++)
#pragma unroll
                for (int nf = 0; nf < 4; nf++) {
                    mma_tf32(acc[mf][nf], ahi[mf], bhi[nf]);
                    mma_tf32(acc[mf][nf], ahi[mf], blo[nf]);
                    mma_tf32(acc[mf][nf], alo[mf], bhi[nf]);
                }
        }
        __syncthreads();
    }
}

// Epilogue coordinate helper (per fragment register). Variadic so the body
// may contain commas.
#define EPI_LOOP(ROW_EXPR, COL_EXPR, ...)                                    \
    {                                                                        \
        const int lane = threadIdx.x & 31;                                   \
        const int warp = threadIdx.x >> 5;                                   \
        const int gid = lane >> 2, tig = lane & 3;                           \
        const int wm = (warp >> 2) * 64, wn = (warp & 3) * 32;               \
        _Pragma("unroll") for (int mf = 0; mf < 4; mf++)                     \
        _Pragma("unroll") for (int nf = 0; nf < 4; nf++)                     \
        _Pragma("unroll") for (int r = 0; r < 4; r++) {                      \
            int row = (ROW_EXPR) + wm + mf * 16 + gid + ((r >> 1) * 8);      \
            int col = (COL_EXPR) + wn + nf * 8 + tig * 2 + (r & 1);          \
            float val = acc[mf][nf][r];                                      \
            __VA_ARGS__                                                      \
        }                                                                    \
    }

// ---------------------------------------------------------------------------
// Projections: out = hs @ W + bias, optional scatter to [B,NH,T,D]
// ---------------------------------------------------------------------------
__global__ void __launch_bounds__(256)
proj_mma(const float* __restrict__ A, const float* __restrict__ W,
         const float* __restrict__ bias, float* __restrict__ out,
         int N, int Kdim, int NH)
{
    const int m0 = blockIdx.y * 128, n0 = blockIdx.x * 128;
    float acc[4][4][4] = {};
    gemm_core<false>(A, W, Kdim, Kdim, N, m0, n0, acc);

    EPI_LOOP(m0, n0, {
        val += bias ? bias[col] : 0.f;
        if (NH > 0) {
            int b = row / T;
            int t = row % T;
            int h = col >> 7;
            int d = col & 127;
            out[(((size_t)(b * NH + h)) * T + t) * D + d] = val;
        } else {
            out[(size_t)row * N + col] = val;
        }
    })
}

// ---------------------------------------------------------------------------
// Scores: S = SCALE * Q K^T + additive prefix-causal bias
// ---------------------------------------------------------------------------
__global__ void __launch_bounds__(256)
scores_mma(const float* __restrict__ q, const float* __restrict__ k,
           float* __restrict__ s)
{
    const int bh = blockIdx.z;
    const int b = bh / H, h = bh % H;
    const float* Q  = q + (size_t)(b * H + h) * T * D;
    const float* Kp = k + (size_t)(b * KV + h / GROUPS) * T * D;
    float* S = s + (size_t)bh * T * T;

    const int m0 = blockIdx.y * 128, n0 = blockIdx.x * 128;
    float acc[4][4][4] = {};
    gemm_core<true>(Q, Kp, D, D, D, m0, n0, acc);

    EPI_LOOP(m0, n0, {
        float bias = ((col < LP) || (row >= LP && col <= row)) ? 1.0f : 0.0f;
        S[(size_t)row * T + col] = val * SCALE + bias;
    })
}

// ---------------------------------------------------------------------------
// PV: O[b,t,h*D+d] = P @ V
// ---------------------------------------------------------------------------
__global__ void __launch_bounds__(256)
pv_mma(const float* __restrict__ s, const float* __restrict__ v,
       float* __restrict__ o)
{
    const int bh = blockIdx.z;
    const int b = bh / H, h = bh % H;
    const float* P = s + (size_t)bh * T * T;
    const float* V = v + (size_t)(b * KV + h / GROUPS) * T * D;

    const int m0 = blockIdx.y * 128, n0 = 0;
    float acc[4][4][4] = {};
    gemm_core<false>(P, V, T, T, D, m0, n0, acc);

    EPI_LOOP(m0, n0, {
        o[((size_t)b * T + row) * (H * D) + h * D + col] = val;
    })
}

// ---------------------------------------------------------------------------
// RoPE on [B,NH,T,D], positions t >= LP.
// ---------------------------------------------------------------------------
__global__ void __launch_bounds__(256)
rope_kernel(float* __restrict__ x, const float* __restrict__ cosp,
            const float* __restrict__ sinp, int NH)
{
    int idx = blockIdx.x * 256 + threadIdx.x;
    int d = idx & 63;
    int rest = idx >> 6;
    int t = rest % LSEQ + LP;
    int bh = rest / LSEQ;
    int b = bh / NH, h = bh % NH;

    size_t base  = ((size_t)(b * NH + h) * T + t) * D;
    size_t cbase = ((size_t)b * LSEQ + (t - LP)) * D;

    float x1 = x[base + d], x2 = x[base + d + 64];
    float c1 = cosp[cbase + d],      s1 = sinp[cbase + d];
    float c2 = cosp[cbase + d + 64], s2 = sinp[cbase + d + 64];
    x[base + d]      = x1 * c1 - x2 * s1;
    x[base + d + 64] = x2 * c2 + x1 * s2;
}

// ---------------------------------------------------------------------------
// Row softmax over T=2048. One block (256 thr) per row.
// ---------------------------------------------------------------------------
__global__ void __launch_bounds__(256)
softmax_rows(float* __restrict__ s)
{
    float* row = s + (size_t)blockIdx.x * T;
    __shared__ float red[256];
    int tid = threadIdx.x;

    float v[8];
    float mx = -1e30f;
#pragma unroll
    for (int i = 0; i < 8; i++) { v[i] = row[tid + i * 256]; mx = fmaxf(mx, v[i]); }
    red[tid] = mx; __syncthreads();
    for (int st = 128; st > 0; st >>= 1) {
        if (tid < st) red[tid] = fmaxf(red[tid], red[tid + st]);
        __syncthreads();
    }
    mx = red[0]; __syncthreads();

    float sum = 0.f;
#pragma unroll
    for (int i = 0; i < 8; i++) { v[i] = __expf(v[i] - mx); sum += v[i]; }
    red[tid] = sum; __syncthreads();
    for (int st = 128; st > 0; st >>= 1) {
        if (tid < st) red[tid] += red[tid + st];
        __syncthreads();
    }
    float inv = 1.0f / red[0];
#pragma unroll
    for (int i = 0; i < 8; i++) row[tid + i * 256] = v[i] * inv;
}

// ---------------------------------------------------------------------------
// Launch
// ---------------------------------------------------------------------------
extern "C" void kernel_launch(void* const* d_in, const int* in_sizes, int n_in,
                              void* d_out, int out_size)
{
    (void)in_sizes; (void)n_in; (void)out_size;
    const float* hs   = (const float*)d_in[0];
    const float* cosp = (const float*)d_in[1];
    const float* sinp = (const float*)d_in[2];
    const float* Wq   = (const float*)d_in[3];
    const float* bq   = (const float*)d_in[4];
    const float* Wk   = (const float*)d_in[5];
    const float* bk   = (const float*)d_in[6];
    const float* Wv   = (const float*)d_in[7];
    const float* bv   = (const float*)d_in[8];
    const float* Wo   = (const float*)d_in[9];
    float* out = (float*)d_out;

    float *q, *k, *v, *s, *o;
    cudaGetSymbolAddress((void**)&q, g_q);
    cudaGetSymbolAddress((void**)&k, g_k);
    cudaGetSymbolAddress((void**)&v, g_v);
    cudaGetSymbolAddress((void**)&s, g_s);
    cudaGetSymbolAddress((void**)&o, g_o);

    const int M = B * T;  // 4096

    // QKV projections (tensor cores, scatter to [B,heads,T,D])
    proj_mma<<<dim3((H * D) / 128, M / 128), 256>>>(hs, Wq, bq, q, H * D, C, H);
    proj_mma<<<dim3((KV * D) / 128, M / 128), 256>>>(hs, Wk, bk, k, KV * D, C, KV);
    proj_mma<<<dim3((KV * D) / 128, M / 128), 256>>>(hs, Wv, bv, v, KV * D, C, KV);

    // RoPE
    rope_kernel<<<(B * H * LSEQ * 64) / 256, 256>>>(q, cosp, sinp, H);
    rope_kernel<<<(B * KV * LSEQ * 64) / 256, 256>>>(k, cosp, sinp, KV);

    // Scores
    scores_mma<<<dim3(T / 128, T / 128, B * H), 256>>>(q, k, s);

    // Softmax
    softmax_rows<<<B * H * T, 256>>>(s);

    // PV
    pv_mma<<<dim3(1, T / 128, B * H), 256>>>(s, v, o);

    // Output projection
    proj_mma<<<dim3(C / 128, M / 128), 256>>>(o, Wo, nullptr, out, C, H * D, 0);
}

// round 5
// speedup vs baseline: 1.2806x; 1.0002x over previous
#include <cuda_runtime.h>
#include <cuda_bf16.h>
#include <math.h>
#include <stdint.h>

#define B   2
#define T   2048
#define C   2048
#define H   16
#define KV  4
#define D   128
#define LP  64
#define GROUPS (H / KV)
#define LSEQ (T - LP)            // 1984
#define SCALE 0.08838834764831845f   // 1/sqrt(128)

// ---------------- scratch (static device globals: allowed) ----------------
__device__ float g_q[(size_t)B * H * T * D];          // [B,H,T,D]
__device__ float g_k[(size_t)B * KV * T * D];         // [B,KV,T,D]
__device__ float g_v[(size_t)B * KV * T * D];         // [B,KV,T,D]
__device__ float g_s[(size_t)B * H * T * T];          // [B,H,T,T] 537 MB
__device__ float g_o[(size_t)B * T * H * D];          // [B,T,H*D]

// ---------------------------------------------------------------------------
// tf32 helpers
// ---------------------------------------------------------------------------
__device__ __forceinline__ uint32_t f2tf(float x) {
    uint32_t r;
    asm("cvt.rna.tf32.f32 %0, %1;" : "=r"(r) : "f"(x));
    return r;
}

__device__ __forceinline__ void mma_tf32(float c[4],
                                         const uint32_t a[4],
                                         const uint32_t b[2]) {
    asm volatile(
        "mma.sync.aligned.m16n8k8.row.col.f32.tf32.tf32.f32 "
        "{%0,%1,%2,%3},{%4,%5,%6,%7},{%8,%9},{%0,%1,%2,%3};"
        : "+f"(c[0]), "+f"(c[1]), "+f"(c[2]), "+f"(c[3])
        : "r"(a[0]), "r"(a[1]), "r"(a[2]), "r"(a[3]), "r"(b[0]), "r"(b[1]));
}

// ---------------------------------------------------------------------------
// Core: 128x128 output tile, K-loop step 16, 256 threads (8 warps, 2x4 layout,
// 64x32 warp tile). 3xTF32 split for fp32-level accuracy.
// A: row-major [*, lda], tile rows m0.. ; B:
//   TRANSB=false: row-major [k][n] with stride ldb (tile cols n0..)
//   TRANSB=true : row-major [n][k] with stride ldb (i.e. B^T; tile rows n0..)
// ---------------------------------------------------------------------------
template<bool TRANSB>
__device__ __forceinline__ void gemm_core(const float* __restrict__ A,
                                          const float* __restrict__ Bm,
                                          int Kdim, int lda, int ldb,
                                          int m0, int n0,
                                          float acc[4][4][4])
{
    __shared__ float As[16][136];
    __shared__ float Bs[16][136];

    const int tid  = threadIdx.x;
    const int lane = tid & 31;
    const int warp = tid >> 5;
    const int gid  = lane >> 2;        // 0..7
    const int tig  = lane & 3;         // 0..3
    const int wm   = (warp >> 2) * 64; // warp M offset (0/64)
    const int wn   = (warp & 3) * 32;  // warp N offset (0/32/64/96)

    const int ar  = tid >> 2;          // 0..63 (A/B^T tile row)
    const int ac4 = (tid & 3) * 4;     // k offset, float4
    const int br  = tid >> 4;          // 0..15 (row-major B k row)
    const int bc  = (tid & 15) * 4;    // n offset, float4

    for (int k0 = 0; k0 < Kdim; k0 += 16) {
        // ---- load A tile (transposed into [k][m]) ----
#pragma unroll
        for (int half = 0; half < 2; half++) {
            int row = ar + half * 64;
            float4 v = *reinterpret_cast<const float4*>(
                &A[(size_t)(m0 + row) * lda + k0 + ac4]);
            As[ac4 + 0][row] = v.x; As[ac4 + 1][row] = v.y;
            As[ac4 + 2][row] = v.z; As[ac4 + 3][row] = v.w;
        }
        // ---- load B tile into [k][n] ----
        if (TRANSB) {
#pragma unroll
            for (int half = 0; half < 2; half++) {
                int row = ar + half * 64;
                float4 v = *reinterpret_cast<const float4*>(
                    &Bm[(size_t)(n0 + row) * ldb + k0 + ac4]);
                Bs[ac4 + 0][row] = v.x; Bs[ac4 + 1][row] = v.y;
                Bs[ac4 + 2][row] = v.z; Bs[ac4 + 3][row] = v.w;
            }
        } else {
#pragma unroll
            for (int half = 0; half < 2; half++) {
                *reinterpret_cast<float4*>(&Bs[br][bc + half * 64]) =
                    *reinterpret_cast<const float4*>(
                        &Bm[(size_t)(k0 + br) * ldb + n0 + bc + half * 64]);
            }
        }
        __syncthreads();

#pragma unroll
        for (int ks = 0; ks < 2; ks++) {
            uint32_t ahi[4][4], alo[4][4];
#pragma unroll
            for (int mf = 0; mf < 4; mf++)
#pragma unroll
                for (int r = 0; r < 4; r++) {
                    int krow = ks * 8 + tig + (r >> 1) * 4;
                    int mcol = wm + mf * 16 + gid + (r & 1) * 8;
                    float a = As[krow][mcol];
                    uint32_t hi = f2tf(a);
                    ahi[mf][r] = hi;
                    alo[mf][r] = f2tf(a - __uint_as_float(hi));
                }
            uint32_t bhi[4][2], blo[4][2];
#pragma unroll
            for (int nf = 0; nf < 4; nf++)
#pragma unroll
                for (int r = 0; r < 2; r++) {
                    int krow = ks * 8 + tig + r * 4;
                    int ncol = wn + nf * 8 + gid;
                    float b = Bs[krow][ncol];
                    uint32_t hi = f2tf(b);
                    bhi[nf][r] = hi;
                    blo[nf][r] = f2tf(b - __uint_as_float(hi));
                }
#pragma unroll
            for (int mf = 0; mf < 4; mf++)
#pragma unroll
                for (int nf = 0; nf < 4; nf++) {
                    mma_tf32(acc[mf][nf], ahi[mf], bhi[nf]);
                    mma_tf32(acc[mf][nf], ahi[mf], blo[nf]);
                    mma_tf32(acc[mf][nf], alo[mf], bhi[nf]);
                }
        }
        __syncthreads();
    }
}

// Epilogue coordinate helper (per fragment register). Variadic so the body
// may contain commas.
#define EPI_LOOP(ROW_EXPR, COL_EXPR, ...)                                    \
    {                                                                        \
        const int lane = threadIdx.x & 31;                                   \
        const int warp = threadIdx.x >> 5;                                   \
        const int gid = lane >> 2, tig = lane & 3;                           \
        const int wm = (warp >> 2) * 64, wn = (warp & 3) * 32;               \
        _Pragma("unroll") for (int mf = 0; mf < 4; mf++)                     \
        _Pragma("unroll") for (int nf = 0; nf < 4; nf++)                     \
        _Pragma("unroll") for (int r = 0; r < 4; r++) {                      \
            int row = (ROW_EXPR) + wm + mf * 16 + gid + ((r >> 1) * 8);      \
            int col = (COL_EXPR) + wn + nf * 8 + tig * 2 + (r & 1);          \
            float val = acc[mf][nf][r];                                      \
            __VA_ARGS__                                                      \
        }                                                                    \
    }

// ---------------------------------------------------------------------------
// Projections: out = hs @ W + bias, optional scatter to [B,NH,T,D]
// ---------------------------------------------------------------------------
__global__ void __launch_bounds__(256)
proj_mma(const float* __restrict__ A, const float* __restrict__ W,
         const float* __restrict__ bias, float* __restrict__ out,
         int N, int Kdim, int NH)
{
    const int m0 = blockIdx.y * 128, n0 = blockIdx.x * 128;
    float acc[4][4][4] = {};
    gemm_core<false>(A, W, Kdim, Kdim, N, m0, n0, acc);

    EPI_LOOP(m0, n0, {
        val += bias ? bias[col] : 0.f;
        if (NH > 0) {
            int b = row / T;
            int t = row % T;
            int h = col >> 7;
            int d = col & 127;
            out[(((size_t)(b * NH + h)) * T + t) * D + d] = val;
        } else {
            out[(size_t)row * N + col] = val;
        }
    })
}

// ---------------------------------------------------------------------------
// Scores: S = SCALE * Q K^T + additive prefix-causal bias
// ---------------------------------------------------------------------------
__global__ void __launch_bounds__(256)
scores_mma(const float* __restrict__ q, const float* __restrict__ k,
           float* __restrict__ s)
{
    const int bh = blockIdx.z;
    const int b = bh / H, h = bh % H;
    const float* Q  = q + (size_t)(b * H + h) * T * D;
    const float* Kp = k + (size_t)(b * KV + h / GROUPS) * T * D;
    float* S = s + (size_t)bh * T * T;

    const int m0 = blockIdx.y * 128, n0 = blockIdx.x * 128;
    float acc[4][4][4] = {};
    gemm_core<true>(Q, Kp, D, D, D, m0, n0, acc);

    EPI_LOOP(m0, n0, {
        float bias = ((col < LP) || (row >= LP && col <= row)) ? 1.0f : 0.0f;
        S[(size_t)row * T + col] = val * SCALE + bias;
    })
}

// ---------------------------------------------------------------------------
// PV: O[b,t,h*D+d] = P @ V
// ---------------------------------------------------------------------------
__global__ void __launch_bounds__(256)
pv_mma(const float* __restrict__ s, const float* __restrict__ v,
       float* __restrict__ o)
{
    const int bh = blockIdx.z;
    const int b = bh / H, h = bh % H;
    const float* P = s + (size_t)bh * T * T;
    const float* V = v + (size_t)(b * KV + h / GROUPS) * T * D;

    const int m0 = blockIdx.y * 128, n0 = 0;
    float acc[4][4][4] = {};
    gemm_core<false>(P, V, T, T, D, m0, n0, acc);

    EPI_LOOP(m0, n0, {
        o[((size_t)b * T + row) * (H * D) + h * D + col] = val;
    })
}

// ---------------------------------------------------------------------------
// RoPE on [B,NH,T,D], positions t >= LP.
// ---------------------------------------------------------------------------
__global__ void __launch_bounds__(256)
rope_kernel(float* __restrict__ x, const float* __restrict__ cosp,
            const float* __restrict__ sinp, int NH)
{
    int idx = blockIdx.x * 256 + threadIdx.x;
    int d = idx & 63;
    int rest = idx >> 6;
    int t = rest % LSEQ + LP;
    int bh = rest / LSEQ;
    int b = bh / NH, h = bh % NH;

    size_t base  = ((size_t)(b * NH + h) * T + t) * D;
    size_t cbase = ((size_t)b * LSEQ + (t - LP)) * D;

    float x1 = x[base + d], x2 = x[base + d + 64];
    float c1 = cosp[cbase + d],      s1 = sinp[cbase + d];
    float c2 = cosp[cbase + d + 64], s2 = sinp[cbase + d + 64];
    x[base + d]      = x1 * c1 - x2 * s1;
    x[base + d + 64] = x2 * c2 + x1 * s2;
}

// ---------------------------------------------------------------------------
// Row softmax over T=2048. One block (256 thr) per row.
// ---------------------------------------------------------------------------
__global__ void __launch_bounds__(256)
softmax_rows(float* __restrict__ s)
{
    float* row = s + (size_t)blockIdx.x * T;
    __shared__ float red[256];
    int tid = threadIdx.x;

    float v[8];
    float mx = -1e30f;
#pragma unroll
    for (int i = 0; i < 8; i++) { v[i] = row[tid + i * 256]; mx = fmaxf(mx, v[i]); }
    red[tid] = mx; __syncthreads();
    for (int st = 128; st > 0; st >>= 1) {
        if (tid < st) red[tid] = fmaxf(red[tid], red[tid + st]);
        __syncthreads();
    }
    mx = red[0]; __syncthreads();

    float sum = 0.f;
#pragma unroll
    for (int i = 0; i < 8; i++) { v[i] = __expf(v[i] - mx); sum += v[i]; }
    red[tid] = sum; __syncthreads();
    for (int st = 128; st > 0; st >>= 1) {
        if (tid < st) red[tid] += red[tid + st];
        __syncthreads();
    }
    float inv = 1.0f / red[0];
#pragma unroll
    for (int i = 0; i < 8; i++) row[tid + i * 256] = v[i] * inv;
}

// ---------------------------------------------------------------------------
// Launch
// ---------------------------------------------------------------------------
extern "C" void kernel_launch(void* const* d_in, const int* in_sizes, int n_in,
                              void* d_out, int out_size)
{
    (void)in_sizes; (void)n_in; (void)out_size;
    const float* hs   = (const float*)d_in[0];
    const float* cosp = (const float*)d_in[1];
    const float* sinp = (const float*)d_in[2];
    const float* Wq   = (const float*)d_in[3];
    const float* bq   = (const float*)d_in[4];
    const float* Wk   = (const float*)d_in[5];
    const float* bk   = (const float*)d_in[6];
    const float* Wv   = (const float*)d_in[7];
    const float* bv   = (const float*)d_in[8];
    const float* Wo   = (const float*)d_in[9];
    float* out = (float*)d_out;

    float *q, *k, *v, *s, *o;
    cudaGetSymbolAddress((void**)&q, g_q);
    cudaGetSymbolAddress((void**)&k, g_k);
    cudaGetSymbolAddress((void**)&v, g_v);
    cudaGetSymbolAddress((void**)&s, g_s);
    cudaGetSymbolAddress((void**)&o, g_o);

    const int M = B * T;  // 4096

    // QKV projections (tensor cores, scatter to [B,heads,T,D])
    proj_mma<<<dim3((H * D) / 128, M / 128), 256>>>(hs, Wq, bq, q, H * D, C, H);
    proj_mma<<<dim3((KV * D) / 128, M / 128), 256>>>(hs, Wk, bk, k, KV * D, C, KV);
    proj_mma<<<dim3((KV * D) / 128, M / 128), 256>>>(hs, Wv, bv, v, KV * D, C, KV);

    // RoPE
    rope_kernel<<<(B * H * LSEQ * 64) / 256, 256>>>(q, cosp, sinp, H);
    rope_kernel<<<(B * KV * LSEQ * 64) / 256, 256>>>(k, cosp, sinp, KV);

    // Scores
    scores_mma<<<dim3(T / 128, T / 128, B * H), 256>>>(q, k, s);

    // Softmax
    softmax_rows<<<B * H * T, 256>>>(s);

    // PV
    pv_mma<<<dim3(1, T / 128, B * H), 256>>>(s, v, o);

    // Output projection
    proj_mma<<<dim3(C / 128, M / 128), 256>>>(o, Wo, nullptr, out, C, H * D, 0);
}